// round 4
// baseline (speedup 1.0000x reference)
#include <cuda_runtime.h>
#include <math.h>

#define N_NODES 10000
#define N_EDGES 160000
#define N_GRAPHS 64
#define HID 128
#define LAT 64
#define NLAY 3
#define ET 32          // edges per block in the edge kernel

typedef unsigned long long u64;

// ---------------- device scratch (no allocations allowed) ----------------
__device__ float d_h[N_NODES * HID];
__device__ float d_aggr[N_NODES * HID];
__device__ float2 d_W1p[NLAY * 128 * 256];   // msg1_W k-pair packed: [l][kp][j] = (w[2kp][j], w[2kp+1][j])
__device__ float  d_W1tail[NLAY * 256];      // k=256 column (edge_attr weight)
__device__ float2 d_W2p[NLAY * 128 * 128];   // msg2_W k-pair packed: [l][kp][i]
__device__ float  d_Wgt[NLAY * 256 * HID];   // gate_W transposed: [l][k(256)][j(128)]
__device__ float  d_sums[N_GRAPHS * HID];
__device__ float  d_counts[N_GRAPHS];

__device__ __forceinline__ float sigmoidf_(float v) {
    return 1.f / (1.f + __expf(-v));
}
__device__ __forceinline__ void ffma2(u64& d, u64 a, u64 b) {
    asm("fma.rn.f32x2 %0, %1, %2, %0;" : "+l"(d) : "l"(a), "l"(b));
}
__device__ __forceinline__ float hadd2(u64 v) {
    float lo, hi;
    asm("mov.b64 {%0, %1}, %2;" : "=f"(lo), "=f"(hi) : "l"(v));
    return lo + hi;
}

// block-wide sum over blockDim.x==128 threads
__device__ __forceinline__ float block_sum128(float v, float* red, int j) {
    red[j] = v;
    __syncthreads();
    #pragma unroll
    for (int s = 64; s > 0; s >>= 1) {
        if (j < s) red[j] += red[j + s];
        __syncthreads();
    }
    float r = red[0];
    __syncthreads();
    return r;
}

// ---------------- weight repack (run once per launch) ----------------
__global__ void transpose_kernel(const float* __restrict__ W1,   // [3][256][257]
                                 const float* __restrict__ W2,   // [3][128][256]
                                 const float* __restrict__ Wg) { // [3][128][256]
    int idx = blockIdx.x * blockDim.x + threadIdx.x;
    int stride = gridDim.x * blockDim.x;
    // W1 -> packed k pairs
    const int n1 = NLAY * 128 * 256;
    for (int t = idx; t < n1; t += stride) {
        int l = t / (128 * 256);
        int r = t % (128 * 256);
        int kp = r / 256;
        int j = r % 256;
        const float* src = W1 + (l * 256 + j) * 257 + 2 * kp;
        d_W1p[t] = make_float2(src[0], src[1]);
    }
    // W1 tail column (k = 256)
    for (int t = idx; t < NLAY * 256; t += stride) {
        int l = t / 256;
        int j = t % 256;
        d_W1tail[t] = W1[(l * 256 + j) * 257 + 256];
    }
    // W2 -> packed k pairs
    const int n2 = NLAY * 128 * 128;
    for (int t = idx; t < n2; t += stride) {
        int l = t / (128 * 128);
        int r = t % (128 * 128);
        int kp = r / 128;
        int i = r % 128;
        const float* src = W2 + (l * 128 + i) * 256 + 2 * kp;
        d_W2p[t] = make_float2(src[0], src[1]);
    }
    // gate weights: plain transpose (used by node_kernel)
    const int n3 = NLAY * 128 * 256;
    for (int t = idx; t < n3; t += stride) {
        int l = t / (128 * 256);
        int r = t % (128 * 256);
        int i = r / 256;
        int k = r % 256;
        d_Wgt[l * 256 * 128 + k * 128 + i] = Wg[t];
    }
}

// ---------------- node embedding: h = silu(LN(x @ W.T + b)) ----------------
__global__ void embed_kernel(const float* __restrict__ x,
                             const float* __restrict__ W,   // [128][3]
                             const float* __restrict__ b,
                             const float* __restrict__ lng,
                             const float* __restrict__ lnb) {
    __shared__ float red[HID];
    int n = blockIdx.x;
    int j = threadIdx.x;
    float x0 = x[n * 3 + 0], x1 = x[n * 3 + 1], x2 = x[n * 3 + 2];
    float v = b[j] + x0 * W[j * 3 + 0] + x1 * W[j * 3 + 1] + x2 * W[j * 3 + 2];
    float m = block_sum128(v, red, j) * (1.f / HID);
    float d = v - m;
    float var = block_sum128(d * d, red, j) * (1.f / HID);
    float y = d * rsqrtf(var + 1e-5f) * lng[j] + lnb[j];
    d_h[n * HID + j] = y * sigmoidf_(y);
}

// ---------------- zero scratch ----------------
__global__ void zero_aggr_kernel() {
    int idx = blockIdx.x * blockDim.x + threadIdx.x;
    int stride = gridDim.x * blockDim.x;
    for (int t = idx; t < N_NODES * HID; t += stride) d_aggr[t] = 0.f;
}
__global__ void zero_pool_kernel() {
    int idx = blockIdx.x * blockDim.x + threadIdx.x;
    if (idx < N_GRAPHS * HID) d_sums[idx] = 0.f;
    if (idx < N_GRAPHS) d_counts[idx] = 0.f;
}

// ---------------- edge MLP + scatter-add (the hot kernel) ----------------
// block = 256 threads, ET=32 edges/block. Packed f32x2 math (FFMA2):
// accumulators hold dual partial sums over (even k, odd k); horizontal add at end.
// GEMM1: 128 j-threads x 2 edge-groups; thread owns cols {j, j+128} x 16 edges.
// GEMM2: 64 i-threads x 4 edge-groups; thread owns cols {i, i+64} x 8 edges.
__global__ void __launch_bounds__(256) edge_kernel(
    const float* __restrict__ edge_attr,
    const int* __restrict__ edge_index,
    const float* __restrict__ b1_all,   // [3][256]
    const float* __restrict__ b2_all,   // [3][128]
    int l) {
    // zbuf doubles as: z [32][260] (33280 B) then m1 [32][256] (32768 B)
    __shared__ __align__(16) float zbuf[ET * 260];
    __shared__ int dst_s[ET];
    __shared__ int src_s[ET];

    const int tid = threadIdx.x;
    const int e0 = blockIdx.x * ET;
    const float2* W1p = d_W1p + l * 128 * 256;
    const float2* W2p = d_W2p + l * 128 * 128;

    if (tid < ET)                dst_s[tid]       = edge_index[N_EDGES + e0 + tid];
    else if (tid < 2 * ET)       src_s[tid - ET]  = edge_index[e0 + tid - ET];
    __syncthreads();

    // stage z = [h[dst] | h[src] | ea]
    for (int e = 0; e < ET; ++e) {
        float v;
        if (tid < HID) v = d_h[dst_s[e] * HID + tid];
        else           v = d_h[src_s[e] * HID + (tid - HID)];
        zbuf[e * 260 + tid] = v;
        if (tid == 0) zbuf[e * 260 + 256] = edge_attr[e0 + e];
    }
    __syncthreads();

    // ---- GEMM1 (packed over k) ----
    const int j1 = tid & 127;          // column (also col j1+128)
    const int eg1 = (tid >> 7) * 16;   // 16-edge group base
    u64 accA[16], accB[16];
    #pragma unroll
    for (int e = 0; e < 16; ++e) { accA[e] = 0ull; accB[e] = 0ull; }

    #pragma unroll 1
    for (int kc = 0; kc < 64; ++kc) {      // 4 k per chunk = 2 k-pairs
        const int kp = kc * 2;
        u64 wA0 = *(const u64*)&W1p[(kp    ) * 256 + j1];
        u64 wA1 = *(const u64*)&W1p[(kp + 1) * 256 + j1];
        u64 wB0 = *(const u64*)&W1p[(kp    ) * 256 + j1 + 128];
        u64 wB1 = *(const u64*)&W1p[(kp + 1) * 256 + j1 + 128];
        #pragma unroll
        for (int e = 0; e < 16; ++e) {
            const float* zr = &zbuf[(eg1 + e) * 260 + kc * 4];
            u64 z0 = *(const u64*)&zr[0];
            u64 z1 = *(const u64*)&zr[2];
            ffma2(accA[e], z0, wA0);
            ffma2(accA[e], z1, wA1);
            ffma2(accB[e], z0, wB0);
            ffma2(accB[e], z1, wB1);
        }
    }
    float bA  = b1_all[l * 256 + j1];
    float bB  = b1_all[l * 256 + j1 + 128];
    float wtA = d_W1tail[l * 256 + j1];
    float wtB = d_W1tail[l * 256 + j1 + 128];
    float outA[16], outB[16];
    #pragma unroll
    for (int e = 0; e < 16; ++e) {
        float zl = zbuf[(eg1 + e) * 260 + 256];
        float vA = hadd2(accA[e]) + fmaf(zl, wtA, bA);
        float vB = hadd2(accB[e]) + fmaf(zl, wtB, bB);
        outA[e] = vA * sigmoidf_(vA);
        outB[e] = vB * sigmoidf_(vB);
    }
    __syncthreads();   // all z reads complete before overwriting buffer

    // store m1 as [e][256]
    #pragma unroll
    for (int e = 0; e < 16; ++e) {
        zbuf[(eg1 + e) * 256 + j1]       = outA[e];
        zbuf[(eg1 + e) * 256 + j1 + 128] = outB[e];
    }
    __syncthreads();

    // ---- GEMM2 (packed over jj) ----
    const int i2 = tid & 63;          // column (also col i2+64)
    const int eg2 = (tid >> 6) * 8;   // 8-edge group base
    u64 a2A[8], a2B[8];
    #pragma unroll
    for (int e = 0; e < 8; ++e) { a2A[e] = 0ull; a2B[e] = 0ull; }

    #pragma unroll 1
    for (int kc = 0; kc < 64; ++kc) {
        const int kp = kc * 2;
        u64 wA0 = *(const u64*)&W2p[(kp    ) * 128 + i2];
        u64 wA1 = *(const u64*)&W2p[(kp + 1) * 128 + i2];
        u64 wB0 = *(const u64*)&W2p[(kp    ) * 128 + i2 + 64];
        u64 wB1 = *(const u64*)&W2p[(kp + 1) * 128 + i2 + 64];
        #pragma unroll
        for (int e = 0; e < 8; ++e) {
            const float* mr = &zbuf[(eg2 + e) * 256 + kc * 4];
            u64 m0 = *(const u64*)&mr[0];
            u64 m1 = *(const u64*)&mr[2];
            ffma2(a2A[e], m0, wA0);
            ffma2(a2A[e], m1, wA1);
            ffma2(a2B[e], m0, wB0);
            ffma2(a2B[e], m1, wB1);
        }
    }
    float bi0 = b2_all[l * HID + i2];
    float bi1 = b2_all[l * HID + i2 + 64];
    #pragma unroll
    for (int e = 0; e < 8; ++e) {
        int d = dst_s[eg2 + e];
        atomicAdd(&d_aggr[d * HID + i2],      hadd2(a2A[e]) + bi0);
        atomicAdd(&d_aggr[d * HID + i2 + 64], hadd2(a2B[e]) + bi1);
    }
}

// ---------------- gated node update + residual + LN ----------------
__global__ void node_kernel(const float* __restrict__ gb_all,  // [3][128]
                            const float* __restrict__ lng_all, // [3][128]
                            const float* __restrict__ lnb_all, // [3][128]
                            int l) {
    __shared__ float hn[HID], an[HID], red[HID];
    int n = blockIdx.x;
    int j = threadIdx.x;
    hn[j] = d_h[n * HID + j];
    an[j] = d_aggr[n * HID + j];
    __syncthreads();

    const float* Wg = d_Wgt + l * 256 * HID;
    float g = gb_all[l * HID + j];
    #pragma unroll 4
    for (int k = 0; k < HID; ++k) g = fmaf(hn[k], Wg[k * HID + j], g);
    #pragma unroll 4
    for (int k = 0; k < HID; ++k) g = fmaf(an[k], Wg[(HID + k) * HID + j], g);
    g = sigmoidf_(g);

    float hnew = g * an[j] + (1.f - g) * hn[j];
    float t = hn[j] + hnew;
    float m = block_sum128(t, red, j) * (1.f / HID);
    float d = t - m;
    float var = block_sum128(d * d, red, j) * (1.f / HID);
    d_h[n * HID + j] = d * rsqrtf(var + 1e-5f) * lng_all[l * HID + j] + lnb_all[l * HID + j];
}

// ---------------- pooling: per-graph sums and counts ----------------
__global__ void pool_kernel(const int* __restrict__ batch) {
    int n = blockIdx.x;
    int j = threadIdx.x;
    int g = batch[n];
    atomicAdd(&d_sums[g * HID + j], d_h[n * HID + j]);
    if (j == 0) atomicAdd(&d_counts[g], 1.f);
}

// ---------------- x_global + projector; writes d_out ----------------
// out layout: z_out [64][64] at [0,4096), x_global [64][128] at [4096,12288)
__global__ void final_kernel(const float* __restrict__ W1, const float* __restrict__ b1,
                             const float* __restrict__ g1, const float* __restrict__ bb1,
                             const float* __restrict__ W2, const float* __restrict__ b2,
                             const float* __restrict__ g2, const float* __restrict__ bb2,
                             float* __restrict__ out) {
    __shared__ float xg[HID], p[HID], red[HID];
    int gr = blockIdx.x;
    int j = threadIdx.x;

    float c = d_counts[gr];
    float scale = 1.f / fmaxf(c, 1.f) + 1.f / (c + 1e-6f);
    float v = d_sums[gr * HID + j] * scale;
    xg[j] = v;
    out[N_GRAPHS * LAT + gr * HID + j] = v;   // x_global
    __syncthreads();

    // proj1 + LN + silu
    float a = b1[j];
    #pragma unroll 4
    for (int k = 0; k < HID; ++k) a = fmaf(xg[k], W1[j * HID + k], a);
    float m = block_sum128(a, red, j) * (1.f / HID);
    float d = a - m;
    float var = block_sum128(d * d, red, j) * (1.f / HID);
    a = d * rsqrtf(var + 1e-5f) * g1[j] + bb1[j];
    a = a * sigmoidf_(a);
    p[j] = a;
    __syncthreads();

    // proj2 (64 outputs) + LN over 64
    float z = 0.f;
    if (j < LAT) {
        z = b2[j];
        #pragma unroll 4
        for (int k = 0; k < HID; ++k) z = fmaf(p[k], W2[j * HID + k], z);
    }
    float m2 = block_sum128((j < LAT) ? z : 0.f, red, j) * (1.f / LAT);
    float d2 = z - m2;
    float var2 = block_sum128((j < LAT) ? d2 * d2 : 0.f, red, j) * (1.f / LAT);
    if (j < LAT)
        out[gr * LAT + j] = d2 * rsqrtf(var2 + 1e-5f) * g2[j] + bb2[j];
}

// ---------------- launch ----------------
extern "C" void kernel_launch(void* const* d_in, const int* in_sizes, int n_in,
                              void* d_out, int out_size) {
    const float* x        = (const float*)d_in[0];
    const float* ea       = (const float*)d_in[1];
    const int*   ei       = (const int*)  d_in[2];
    const int*   batch    = (const int*)  d_in[3];
    const float* embW     = (const float*)d_in[4];
    const float* embb     = (const float*)d_in[5];
    const float* embg     = (const float*)d_in[6];
    const float* emblb    = (const float*)d_in[7];
    const float* m1W      = (const float*)d_in[8];
    const float* m1b      = (const float*)d_in[9];
    const float* m2W      = (const float*)d_in[10];
    const float* m2b      = (const float*)d_in[11];
    const float* gW       = (const float*)d_in[12];
    const float* gb       = (const float*)d_in[13];
    const float* lng      = (const float*)d_in[14];
    const float* lnb      = (const float*)d_in[15];
    const float* p1W      = (const float*)d_in[16];
    const float* p1b      = (const float*)d_in[17];
    const float* pl1g     = (const float*)d_in[18];
    const float* pl1b     = (const float*)d_in[19];
    const float* p2W      = (const float*)d_in[20];
    const float* p2b      = (const float*)d_in[21];
    const float* pl2g     = (const float*)d_in[22];
    const float* pl2b     = (const float*)d_in[23];
    float* out = (float*)d_out;

    transpose_kernel<<<384, 256>>>(m1W, m2W, gW);
    embed_kernel<<<N_NODES, HID>>>(x, embW, embb, embg, emblb);

    for (int l = 0; l < NLAY; ++l) {
        zero_aggr_kernel<<<640, 256>>>();
        edge_kernel<<<N_EDGES / ET, 256>>>(ea, ei, m1b, m2b, l);
        node_kernel<<<N_NODES, HID>>>(gb, lng, lnb, l);
    }

    zero_pool_kernel<<<33, 256>>>();
    pool_kernel<<<N_NODES, HID>>>(batch);
    final_kernel<<<N_GRAPHS, HID>>>(p1W, p1b, pl1g, pl1b, p2W, p2b, pl2g, pl2b, out);
}

// round 5
// speedup vs baseline: 2.6822x; 2.6822x over previous
#include <cuda_runtime.h>
#include <cuda_bf16.h>
#include <math.h>

#define N_NODES 10000
#define N_EDGES 160000
#define N_GRAPHS 64
#define HID 128
#define LAT 64
#define NLAY 3
#define ET 64          // edges per block in the edge kernel

// ---------------- device scratch (no allocations allowed) ----------------
__device__ float d_h[N_NODES * HID];
__device__ float d_aggr[N_NODES * HID];
// B-fragment packed weights: per (layer, kstep, ntile, lane) a uint4 {hi01, hi89, lo01, lo89}
__device__ uint4 d_W1f[NLAY * 16 * 32 * 32];   // GEMM1: K=256 (16 steps), N=256 (32 ntiles)
__device__ uint4 d_W2f[NLAY * 16 * 16 * 32];   // GEMM2: K=256 (16 steps), N=128 (16 ntiles)
__device__ float d_W1tail[NLAY * 256];         // k=256 column (edge_attr weight)
__device__ float d_Wgt[NLAY * 256 * HID];      // gate_W transposed
__device__ float d_sums[N_GRAPHS * HID];
__device__ float d_counts[N_GRAPHS];

__device__ __forceinline__ float sigmoidf_(float v) {
    return 1.f / (1.f + __expf(-v));
}
// pack two floats into bf16x2 (lo = first element)
__device__ __forceinline__ unsigned pk2(float lo, float hi) {
    unsigned r;
    asm("cvt.rn.bf16x2.f32 %0, %1, %2;" : "=r"(r) : "f"(hi), "f"(lo));
    return r;
}
__device__ __forceinline__ void mma_bf16(float c[4],
                                         unsigned a0, unsigned a1, unsigned a2, unsigned a3,
                                         unsigned b0, unsigned b1) {
    asm("mma.sync.aligned.m16n8k16.row.col.f32.bf16.bf16.f32 "
        "{%0,%1,%2,%3}, {%4,%5,%6,%7}, {%8,%9}, {%0,%1,%2,%3};"
        : "+f"(c[0]), "+f"(c[1]), "+f"(c[2]), "+f"(c[3])
        : "r"(a0), "r"(a1), "r"(a2), "r"(a3), "r"(b0), "r"(b1));
}

__device__ __forceinline__ float block_sum128(float v, float* red, int j) {
    red[j] = v;
    __syncthreads();
    #pragma unroll
    for (int s = 64; s > 0; s >>= 1) {
        if (j < s) red[j] += red[j + s];
        __syncthreads();
    }
    float r = red[0];
    __syncthreads();
    return r;
}

// ---------------- weight fragment packing (run once per launch) ----------------
__global__ void pack_kernel(const float* __restrict__ W1,   // [3][256][257]
                            const float* __restrict__ W2,   // [3][128][256]
                            const float* __restrict__ Wg) { // [3][128][256]
    int idx = blockIdx.x * blockDim.x + threadIdx.x;
    int stride = gridDim.x * blockDim.x;
    // W1 fragments
    const int n1 = NLAY * 16 * 32 * 32;
    for (int t = idx; t < n1; t += stride) {
        int l = t / (16 * 32 * 32);
        int r = t % (16 * 32 * 32);
        int s = r / (32 * 32);
        int r2 = r % (32 * 32);
        int tt = r2 / 32;
        int lane = r2 % 32;
        int n = tt * 8 + lane / 4;
        int k0 = s * 16 + (lane % 4) * 2;
        const float* row = W1 + (l * 256 + n) * 257;
        float f0 = row[k0], f1 = row[k0 + 1], f2 = row[k0 + 8], f3 = row[k0 + 9];
        unsigned h01 = pk2(f0, f1);
        unsigned h89 = pk2(f2, f3);
        float a0 = __uint_as_float(h01 << 16), a1 = __uint_as_float(h01 & 0xFFFF0000u);
        float a2 = __uint_as_float(h89 << 16), a3 = __uint_as_float(h89 & 0xFFFF0000u);
        uint4 o;
        o.x = h01; o.y = h89;
        o.z = pk2(f0 - a0, f1 - a1);
        o.w = pk2(f2 - a2, f3 - a3);
        d_W1f[t] = o;
    }
    // W2 fragments
    const int n2 = NLAY * 16 * 16 * 32;
    for (int t = idx; t < n2; t += stride) {
        int l = t / (16 * 16 * 32);
        int r = t % (16 * 16 * 32);
        int s = r / (16 * 32);
        int r2 = r % (16 * 32);
        int tt = r2 / 32;
        int lane = r2 % 32;
        int n = tt * 8 + lane / 4;
        int k0 = s * 16 + (lane % 4) * 2;
        const float* row = W2 + (l * 128 + n) * 256;
        float f0 = row[k0], f1 = row[k0 + 1], f2 = row[k0 + 8], f3 = row[k0 + 9];
        unsigned h01 = pk2(f0, f1);
        unsigned h89 = pk2(f2, f3);
        float a0 = __uint_as_float(h01 << 16), a1 = __uint_as_float(h01 & 0xFFFF0000u);
        float a2 = __uint_as_float(h89 << 16), a3 = __uint_as_float(h89 & 0xFFFF0000u);
        uint4 o;
        o.x = h01; o.y = h89;
        o.z = pk2(f0 - a0, f1 - a1);
        o.w = pk2(f2 - a2, f3 - a3);
        d_W2f[t] = o;
    }
    // W1 tail column (k = 256)
    for (int t = idx; t < NLAY * 256; t += stride) {
        int l = t / 256;
        int j = t % 256;
        d_W1tail[t] = W1[(l * 256 + j) * 257 + 256];
    }
    // gate weights transpose
    const int n3 = NLAY * 128 * 256;
    for (int t = idx; t < n3; t += stride) {
        int l = t / (128 * 256);
        int r = t % (128 * 256);
        int i = r / 256;
        int k = r % 256;
        d_Wgt[l * 256 * 128 + k * 128 + i] = Wg[t];
    }
}

// ---------------- node embedding ----------------
__global__ void embed_kernel(const float* __restrict__ x,
                             const float* __restrict__ W,
                             const float* __restrict__ b,
                             const float* __restrict__ lng,
                             const float* __restrict__ lnb) {
    __shared__ float red[HID];
    int n = blockIdx.x;
    int j = threadIdx.x;
    float x0 = x[n * 3 + 0], x1 = x[n * 3 + 1], x2 = x[n * 3 + 2];
    float v = b[j] + x0 * W[j * 3 + 0] + x1 * W[j * 3 + 1] + x2 * W[j * 3 + 2];
    float m = block_sum128(v, red, j) * (1.f / HID);
    float d = v - m;
    float var = block_sum128(d * d, red, j) * (1.f / HID);
    float y = d * rsqrtf(var + 1e-5f) * lng[j] + lnb[j];
    d_h[n * HID + j] = y * sigmoidf_(y);
}

// ---------------- zero scratch ----------------
__global__ void zero_aggr_kernel() {
    int idx = blockIdx.x * blockDim.x + threadIdx.x;
    int stride = gridDim.x * blockDim.x;
    for (int t = idx; t < N_NODES * HID; t += stride) d_aggr[t] = 0.f;
}
__global__ void zero_pool_kernel() {
    int idx = blockIdx.x * blockDim.x + threadIdx.x;
    if (idx < N_GRAPHS * HID) d_sums[idx] = 0.f;
    if (idx < N_GRAPHS) d_counts[idx] = 0.f;
}

// ---------------- edge MLP via tensor cores (split-bf16 3-term) ----------------
// block = 256 threads (8 warps), 64 edges.
// SMEM: Zhi/Zlo bf16x2 word arrays [64 rows][132 words] (reused for m1 after GEMM1).
// GEMM1: warps split N=256 into 8x32 cols; each warp: 4 mtiles x 4 ntiles x 16 ksteps x 3 mma.
// GEMM2: warps split N=128 into 8x16 cols.
__global__ void __launch_bounds__(256) edge_kernel(
    const float* __restrict__ edge_attr,
    const int* __restrict__ edge_index,
    const float* __restrict__ b1_all,   // [3][256]
    const float* __restrict__ b2_all,   // [3][128]
    int l) {
    extern __shared__ __align__(16) unsigned sm[];
    unsigned* Zh = sm;                      // 64*132 words
    unsigned* Zl = sm + 64 * 132;
    int* dst_s = (int*)(sm + 2 * 64 * 132);
    int* src_s = dst_s + 64;
    float* ea_s = (float*)(src_s + 64);

    const int tid = threadIdx.x;
    const int lane = tid & 31, w = tid >> 5;
    const int e0 = blockIdx.x * ET;

    if (tid < 64) { dst_s[tid] = edge_index[N_EDGES + e0 + tid]; ea_s[tid] = edge_attr[e0 + tid]; }
    else if (tid < 128) src_s[tid - 64] = edge_index[e0 + tid - 64];
    __syncthreads();

    // gather + fp32 -> bf16 hi/lo conversion
    {
        int e = tid >> 2, q = tid & 3;
        int node = (q < 2) ? dst_s[e] : src_s[e];
        const float4* hp = (const float4*)(d_h + node * HID + (q & 1) * 64);
        unsigned* oh = Zh + e * 132 + q * 32;
        unsigned* ol = Zl + e * 132 + q * 32;
        #pragma unroll
        for (int i = 0; i < 16; ++i) {
            float4 v = hp[i];
            unsigned h0 = pk2(v.x, v.y), h1 = pk2(v.z, v.w);
            float a0 = __uint_as_float(h0 << 16), a1 = __uint_as_float(h0 & 0xFFFF0000u);
            float a2 = __uint_as_float(h1 << 16), a3 = __uint_as_float(h1 & 0xFFFF0000u);
            oh[i * 2] = h0; oh[i * 2 + 1] = h1;
            ol[i * 2] = pk2(v.x - a0, v.y - a1);
            ol[i * 2 + 1] = pk2(v.z - a2, v.w - a3);
        }
    }
    __syncthreads();

    const int r = lane >> 2, qk = lane & 3;

    // ---- GEMM1 ----
    float c[4][4][4];
    #pragma unroll
    for (int m = 0; m < 4; ++m)
        #pragma unroll
        for (int t = 0; t < 4; ++t)
            #pragma unroll
            for (int k = 0; k < 4; ++k) c[m][t][k] = 0.f;

    for (int s = 0; s < 16; ++s) {
        unsigned Ah[4][4], Al[4][4];
        #pragma unroll
        for (int m = 0; m < 4; ++m) {
            int base = (m * 16 + r) * 132 + s * 8 + qk;
            Ah[m][0] = Zh[base];            Ah[m][2] = Zh[base + 4];
            Ah[m][1] = Zh[base + 8 * 132];  Ah[m][3] = Zh[base + 8 * 132 + 4];
            Al[m][0] = Zl[base];            Al[m][2] = Zl[base + 4];
            Al[m][1] = Zl[base + 8 * 132];  Al[m][3] = Zl[base + 8 * 132 + 4];
        }
        #pragma unroll
        for (int t = 0; t < 4; ++t) {
            uint4 wv = d_W1f[((l * 16 + s) * 32 + (w * 4 + t)) * 32 + lane];
            #pragma unroll
            for (int m = 0; m < 4; ++m)
                mma_bf16(c[m][t], Ah[m][0], Ah[m][1], Ah[m][2], Ah[m][3], wv.x, wv.y);
            #pragma unroll
            for (int m = 0; m < 4; ++m)
                mma_bf16(c[m][t], Ah[m][0], Ah[m][1], Ah[m][2], Ah[m][3], wv.z, wv.w);
            #pragma unroll
            for (int m = 0; m < 4; ++m)
                mma_bf16(c[m][t], Al[m][0], Al[m][1], Al[m][2], Al[m][3], wv.x, wv.y);
        }
    }
    __syncthreads();   // all Z reads complete before overwrite

    // epilogue1: bias + edge_attr tail + silu -> bf16 hi/lo back into Zh/Zl
    #pragma unroll
    for (int m = 0; m < 4; ++m) {
        #pragma unroll
        for (int t = 0; t < 4; ++t) {
            int n0 = (w * 4 + t) * 8 + qk * 2;
            int elo = m * 16 + r, ehi = elo + 8;
            float bn0 = b1_all[l * 256 + n0], bn1 = b1_all[l * 256 + n0 + 1];
            float wt0 = d_W1tail[l * 256 + n0], wt1 = d_W1tail[l * 256 + n0 + 1];
            float el = ea_s[elo], eh = ea_s[ehi];
            float v00 = c[m][t][0] + bn0 + el * wt0;
            float v01 = c[m][t][1] + bn1 + el * wt1;
            float v10 = c[m][t][2] + bn0 + eh * wt0;
            float v11 = c[m][t][3] + bn1 + eh * wt1;
            v00 *= sigmoidf_(v00); v01 *= sigmoidf_(v01);
            v10 *= sigmoidf_(v10); v11 *= sigmoidf_(v11);
            int wlo = elo * 132 + (w * 4 + t) * 4 + qk;
            int whi = ehi * 132 + (w * 4 + t) * 4 + qk;
            unsigned h0 = pk2(v00, v01);
            unsigned h1 = pk2(v10, v11);
            float a0 = __uint_as_float(h0 << 16), a1 = __uint_as_float(h0 & 0xFFFF0000u);
            float a2 = __uint_as_float(h1 << 16), a3 = __uint_as_float(h1 & 0xFFFF0000u);
            Zh[wlo] = h0; Zl[wlo] = pk2(v00 - a0, v01 - a1);
            Zh[whi] = h1; Zl[whi] = pk2(v10 - a2, v11 - a3);
        }
    }
    __syncthreads();

    // ---- GEMM2 ----
    float c2[4][2][4];
    #pragma unroll
    for (int m = 0; m < 4; ++m)
        #pragma unroll
        for (int t = 0; t < 2; ++t)
            #pragma unroll
            for (int k = 0; k < 4; ++k) c2[m][t][k] = 0.f;

    for (int s = 0; s < 16; ++s) {
        unsigned Ah[4][4], Al[4][4];
        #pragma unroll
        for (int m = 0; m < 4; ++m) {
            int base = (m * 16 + r) * 132 + s * 8 + qk;
            Ah[m][0] = Zh[base];            Ah[m][2] = Zh[base + 4];
            Ah[m][1] = Zh[base + 8 * 132];  Ah[m][3] = Zh[base + 8 * 132 + 4];
            Al[m][0] = Zl[base];            Al[m][2] = Zl[base + 4];
            Al[m][1] = Zl[base + 8 * 132];  Al[m][3] = Zl[base + 8 * 132 + 4];
        }
        #pragma unroll
        for (int t = 0; t < 2; ++t) {
            uint4 wv = d_W2f[((l * 16 + s) * 16 + (w * 2 + t)) * 32 + lane];
            #pragma unroll
            for (int m = 0; m < 4; ++m)
                mma_bf16(c2[m][t], Ah[m][0], Ah[m][1], Ah[m][2], Ah[m][3], wv.x, wv.y);
            #pragma unroll
            for (int m = 0; m < 4; ++m)
                mma_bf16(c2[m][t], Ah[m][0], Ah[m][1], Ah[m][2], Ah[m][3], wv.z, wv.w);
            #pragma unroll
            for (int m = 0; m < 4; ++m)
                mma_bf16(c2[m][t], Al[m][0], Al[m][1], Al[m][2], Al[m][3], wv.x, wv.y);
        }
    }

    // epilogue2: bias + scatter-add
    #pragma unroll
    for (int m = 0; m < 4; ++m) {
        #pragma unroll
        for (int t = 0; t < 2; ++t) {
            int i0 = (w * 2 + t) * 8 + qk * 2;
            int elo = m * 16 + r, ehi = elo + 8;
            float bi0 = b2_all[l * 128 + i0], bi1 = b2_all[l * 128 + i0 + 1];
            int dlo = dst_s[elo], dhi = dst_s[ehi];
            atomicAdd(&d_aggr[dlo * HID + i0],     c2[m][t][0] + bi0);
            atomicAdd(&d_aggr[dlo * HID + i0 + 1], c2[m][t][1] + bi1);
            atomicAdd(&d_aggr[dhi * HID + i0],     c2[m][t][2] + bi0);
            atomicAdd(&d_aggr[dhi * HID + i0 + 1], c2[m][t][3] + bi1);
        }
    }
}

// ---------------- gated node update + residual + LN ----------------
__global__ void node_kernel(const float* __restrict__ gb_all,
                            const float* __restrict__ lng_all,
                            const float* __restrict__ lnb_all,
                            int l) {
    __shared__ float hn[HID], an[HID], red[HID];
    int n = blockIdx.x;
    int j = threadIdx.x;
    hn[j] = d_h[n * HID + j];
    an[j] = d_aggr[n * HID + j];
    __syncthreads();

    const float* Wg = d_Wgt + l * 256 * HID;
    float g = gb_all[l * HID + j];
    #pragma unroll 4
    for (int k = 0; k < HID; ++k) g = fmaf(hn[k], Wg[k * HID + j], g);
    #pragma unroll 4
    for (int k = 0; k < HID; ++k) g = fmaf(an[k], Wg[(HID + k) * HID + j], g);
    g = sigmoidf_(g);

    float hnew = g * an[j] + (1.f - g) * hn[j];
    float t = hn[j] + hnew;
    float m = block_sum128(t, red, j) * (1.f / HID);
    float d = t - m;
    float var = block_sum128(d * d, red, j) * (1.f / HID);
    d_h[n * HID + j] = d * rsqrtf(var + 1e-5f) * lng_all[l * HID + j] + lnb_all[l * HID + j];
}

// ---------------- pooling ----------------
__global__ void pool_kernel(const int* __restrict__ batch) {
    int n = blockIdx.x;
    int j = threadIdx.x;
    int g = batch[n];
    atomicAdd(&d_sums[g * HID + j], d_h[n * HID + j]);
    if (j == 0) atomicAdd(&d_counts[g], 1.f);
}

// ---------------- x_global + projector ----------------
__global__ void final_kernel(const float* __restrict__ W1, const float* __restrict__ b1,
                             const float* __restrict__ g1, const float* __restrict__ bb1,
                             const float* __restrict__ W2, const float* __restrict__ b2,
                             const float* __restrict__ g2, const float* __restrict__ bb2,
                             float* __restrict__ out) {
    __shared__ float xg[HID], p[HID], red[HID];
    int gr = blockIdx.x;
    int j = threadIdx.x;

    float c = d_counts[gr];
    float scale = 1.f / fmaxf(c, 1.f) + 1.f / (c + 1e-6f);
    float v = d_sums[gr * HID + j] * scale;
    xg[j] = v;
    out[N_GRAPHS * LAT + gr * HID + j] = v;
    __syncthreads();

    float a = b1[j];
    #pragma unroll 4
    for (int k = 0; k < HID; ++k) a = fmaf(xg[k], W1[j * HID + k], a);
    float m = block_sum128(a, red, j) * (1.f / HID);
    float d = a - m;
    float var = block_sum128(d * d, red, j) * (1.f / HID);
    a = d * rsqrtf(var + 1e-5f) * g1[j] + bb1[j];
    a = a * sigmoidf_(a);
    p[j] = a;
    __syncthreads();

    float z = 0.f;
    if (j < LAT) {
        z = b2[j];
        #pragma unroll 4
        for (int k = 0; k < HID; ++k) z = fmaf(p[k], W2[j * HID + k], z);
    }
    float m2 = block_sum128((j < LAT) ? z : 0.f, red, j) * (1.f / LAT);
    float d2 = z - m2;
    float var2 = block_sum128((j < LAT) ? d2 * d2 : 0.f, red, j) * (1.f / LAT);
    if (j < LAT)
        out[gr * LAT + j] = d2 * rsqrtf(var2 + 1e-5f) * g2[j] + bb2[j];
}

// ---------------- launch ----------------
extern "C" void kernel_launch(void* const* d_in, const int* in_sizes, int n_in,
                              void* d_out, int out_size) {
    const float* x     = (const float*)d_in[0];
    const float* ea    = (const float*)d_in[1];
    const int*   ei    = (const int*)  d_in[2];
    const int*   batch = (const int*)  d_in[3];
    const float* embW  = (const float*)d_in[4];
    const float* embb  = (const float*)d_in[5];
    const float* embg  = (const float*)d_in[6];
    const float* emblb = (const float*)d_in[7];
    const float* m1W   = (const float*)d_in[8];
    const float* m1b   = (const float*)d_in[9];
    const float* m2W   = (const float*)d_in[10];
    const float* m2b   = (const float*)d_in[11];
    const float* gW    = (const float*)d_in[12];
    const float* gb    = (const float*)d_in[13];
    const float* lng   = (const float*)d_in[14];
    const float* lnb   = (const float*)d_in[15];
    const float* p1W   = (const float*)d_in[16];
    const float* p1b   = (const float*)d_in[17];
    const float* pl1g  = (const float*)d_in[18];
    const float* pl1b  = (const float*)d_in[19];
    const float* p2W   = (const float*)d_in[20];
    const float* p2b   = (const float*)d_in[21];
    const float* pl2g  = (const float*)d_in[22];
    const float* pl2b  = (const float*)d_in[23];
    float* out = (float*)d_out;

    const int smem_bytes = 2 * 64 * 132 * 4 + 3 * 64 * 4;   // 68352
    cudaFuncSetAttribute(edge_kernel, cudaFuncAttributeMaxDynamicSharedMemorySize, smem_bytes);

    pack_kernel<<<384, 256>>>(m1W, m2W, gW);
    embed_kernel<<<N_NODES, HID>>>(x, embW, embb, embg, emblb);

    for (int l = 0; l < NLAY; ++l) {
        zero_aggr_kernel<<<640, 256>>>();
        edge_kernel<<<N_EDGES / ET, 256, smem_bytes>>>(ea, ei, m1b, m2b, l);
        node_kernel<<<N_NODES, HID>>>(gb, lng, lnb, l);
    }

    zero_pool_kernel<<<33, 256>>>();
    pool_kernel<<<N_NODES, HID>>>(batch);
    final_kernel<<<N_GRAPHS, HID>>>(p1W, p1b, pl1g, pl1b, p2W, p2b, pl2g, pl2b, out);
}